// round 2
// baseline (speedup 1.0000x reference)
#include <cuda_runtime.h>

#define NN 100000
#define NE 6400000
#define EPSF 1e-8f
#define NU_MOL 1.5e-5f

// Per-node accumulators: [count, div_sum, dpdx, dpdy] [lap_u, lap_v, strain, pad]
__device__ float4 g_acc[NN * 2];
// 0 smooth, 1 mse, 2 div2, 3 mom, 4 prod2, 5 nut2, 6 nwall, 7 bc, 8 wall
__device__ double g_sums[9];

__global__ void zero_kernel() {
    int i = blockIdx.x * blockDim.x + threadIdx.x;
    if (i < NN * 2) g_acc[i] = make_float4(0.f, 0.f, 0.f, 0.f);
    if (i < 9) g_sums[i] = 0.0;
}

__device__ __forceinline__ void red4(float4* p, float a, float b, float c, float d) {
    asm volatile("red.global.add.v4.f32 [%0], {%1,%2,%3,%4};"
                 :: "l"(p), "f"(a), "f"(b), "f"(c), "f"(d) : "memory");
}

__device__ __forceinline__ float warp_sum(float v) {
    #pragma unroll
    for (int o = 16; o > 0; o >>= 1) v += __shfl_down_sync(0xffffffffu, v, o);
    return v;
}

__global__ void __launch_bounds__(256) edge_kernel(
    const float4* __restrict__ pred,
    const float2* __restrict__ attr,
    const int* __restrict__ idx)
{
    float sm = 0.f;
    int stride = gridDim.x * blockDim.x;
    for (int e = blockIdx.x * blockDim.x + threadIdx.x; e < NE; e += stride) {
        int r = idx[e];
        int c = idx[e + NE];
        float4 pr = pred[r];
        float4 pc = pred[c];
        float2 a = attr[e];
        float du = pc.x - pr.x;
        float dv = pc.y - pr.y;
        float dp = pc.z - pr.z;
        float dn = pc.w - pr.w;
        float rdx  = 1.0f / (a.x + EPSF);
        float rdy  = 1.0f / (a.y + EPSF);
        float rdx2 = 1.0f / (a.x * a.x + EPSF);
        float rdy2 = 1.0f / (a.y * a.y + EPSF);
        float dudx = du * rdx, dudy = du * rdy;
        float dvdx = dv * rdx, dvdy = dv * rdy;
        float shear = dudy + dvdx;
        float strain = 2.0f * (dudx * dudx + dvdy * dvdy) + shear * shear;

        red4(&g_acc[2 * r],     1.0f,      dudx + dvdy, dp * rdx, dp * rdy);
        red4(&g_acc[2 * r + 1], du * rdx2, dv * rdy2,   strain,   0.0f);

        sm += du * du + dv * dv + dp * dp + dn * dn;
    }
    // block reduce smooth
    __shared__ float sh[8];
    int lane = threadIdx.x & 31, w = threadIdx.x >> 5;
    float v = warp_sum(sm);
    if (lane == 0) sh[w] = v;
    __syncthreads();
    if (threadIdx.x == 0) {
        float s = 0.f;
        #pragma unroll
        for (int k = 0; k < 8; k++) s += sh[k];
        atomicAdd(&g_sums[0], (double)s);
    }
}

__global__ void __launch_bounds__(256) node_kernel(
    const float4* __restrict__ pred,
    const float4* __restrict__ tgt,
    const unsigned int* __restrict__ wall)   // bool promoted to f32 or i32: nonzero word == true
{
    int i = blockIdx.x * blockDim.x + threadIdx.x;
    float vals[8];
    #pragma unroll
    for (int q = 0; q < 8; q++) vals[q] = 0.f;

    if (i < NN) {
        float4 a0 = g_acc[2 * i];
        float4 a1 = g_acc[2 * i + 1];
        float cnt = fmaxf(a0.x, 1.0f);
        float inv = 1.0f / cnt;
        float4 p = pred[i];
        float4 t = tgt[i];
        float nut = p.w;

        float dvg = a0.y * inv;
        vals[1] = dvg * dvg;                                   // div2

        float pgx = a0.z * inv, pgy = a0.w * inv;
        float lu = a1.x * inv,  lv = a1.y * inv;
        float nueff = NU_MOL + nut;
        float mx = pgx + nueff * lu;
        float my = pgy + nueff * lv;
        vals[2] = mx * mx + my * my;                           // momentum

        float sn = a1.z * inv;
        float prod = nut * sn;
        vals[3] = prod * prod;                                 // production^2

        float d0 = p.x - t.x, d1 = p.y - t.y, d2 = p.z - t.z, d3 = p.w - t.w;
        vals[0] = d0 * d0 + d1 * d1 + d2 * d2 + d3 * d3;       // mse sum

        vals[4] = nut * nut;                                   // dissipation

        float m = (wall[i] != 0u) ? 1.0f : 0.0f;
        float uv = p.x * p.x + p.y * p.y;
        vals[5] = m;                                           // n_wall
        vals[6] = m * uv;                                      // bc
        vals[7] = m * (uv + nut * nut);                        // wall
    }

    __shared__ float sh[8][8];
    int lane = threadIdx.x & 31, w = threadIdx.x >> 5;
    #pragma unroll
    for (int q = 0; q < 8; q++) {
        float v = warp_sum(vals[q]);
        if (lane == 0) sh[q][w] = v;
    }
    __syncthreads();
    if (threadIdx.x < 8) {
        float s = 0.f;
        #pragma unroll
        for (int k = 0; k < 8; k++) s += sh[threadIdx.x][k];
        atomicAdd(&g_sums[threadIdx.x + 1], (double)s);
    }
}

__global__ void final_kernel(float* out) {
    double nw = g_sums[6];
    if (nw < 1.0) nw = 1.0;
    double total =
          1.00 * (g_sums[1] / (4.0 * (double)NN))      // mse
        + 0.10 * (g_sums[2] / (double)NN)              // div
        + 0.10 * (g_sums[3] / (double)NN)              // momentum
        + 0.05 * (g_sums[4] / (double)NN)              // turb production
        + 0.05 * (g_sums[5] / (double)NN)              // turb dissipation
        + 0.05 * (g_sums[7] / nw)                      // bc
        + 0.01 * (g_sums[0] / (4.0 * (double)NE))      // smooth
        + 0.02 * (g_sums[8] / nw);                     // wall
    out[0] = (float)total;
}

extern "C" void kernel_launch(void* const* d_in, const int* in_sizes, int n_in,
                              void* d_out, int out_size) {
    const float4*       pred = (const float4*)d_in[0];
    const float4*       tgt  = (const float4*)d_in[1];
    const float2*       attr = (const float2*)d_in[2];
    const int*          idx  = (const int*)d_in[3];
    const unsigned int* wall = (const unsigned int*)d_in[4];
    float* out = (float*)d_out;

    zero_kernel<<<(NN * 2 + 255) / 256, 256>>>();
    edge_kernel<<<148 * 16, 256>>>(pred, attr, idx);
    node_kernel<<<(NN + 255) / 256, 256>>>(pred, tgt, wall);
    final_kernel<<<1, 1>>>(out);
}